// round 13
// baseline (speedup 1.0000x reference)
#include <cuda_runtime.h>
#include <math.h>

#define S_LEN 4096
#define BATCH 16
#define H2DIM 1024
#define NBLK 148
#define CHUNK 28                                  // ceil(4096/148)
#define ROW_BYTES (BATCH * H2DIM * 4)             // 64KB per s-row
#define SLICE_BYTES (H2DIM * 4)                   // 4KB per (s,b) slice
#define NSTAGE 3
#define FULL_OFF (NSTAGE * ROW_BYTES)             // 3 full mbars
#define EMPTY_OFF (FULL_OFF + NSTAGE * 8)         // 3 empty mbars
#define WBAR_OFF (EMPTY_OFF + NSTAGE * 8)         // weight-prefetch mbar
#define MAIN_SMEM (WBAR_OFF + 8)
#define WEIGHT_SMEM_OFF (2 * ROW_BYTES)           // weights staged over slot 2

// Scratch (allocation-free contract)
__device__ float g_alt[BATCH * H2DIM];            // altered_state (+bias)
__device__ float g_wraw[BATCH * S_LEN];
__device__ float g_m[NBLK * BATCH];
__device__ float g_l[NBLK * BATCH];
__device__ float g_acc[(size_t)NBLK * BATCH * H2DIM];
__device__ unsigned g_bar;                        // up/down grid barrier (self-cleaning)

// ---- packed f32x2 helpers ----------------------------------------------------
__device__ __forceinline__ unsigned long long fma2(unsigned long long a,
                                                   unsigned long long b,
                                                   unsigned long long c) {
    unsigned long long d;
    asm("fma.rn.f32x2 %0, %1, %2, %3;" : "=l"(d) : "l"(a), "l"(b), "l"(c));
    return d;
}
__device__ __forceinline__ unsigned long long mul2(unsigned long long a,
                                                   unsigned long long b) {
    unsigned long long d;
    asm("mul.rn.f32x2 %0, %1, %2;" : "=l"(d) : "l"(a), "l"(b));
    return d;
}
__device__ __forceinline__ unsigned long long pk2(float lo, float hi) {
    unsigned long long r;
    asm("mov.b64 %0, {%1, %2};" : "=l"(r) : "f"(lo), "f"(hi));
    return r;
}
__device__ __forceinline__ float2 upk2(unsigned long long v) {
    float2 r;
    asm("mov.b64 {%0, %1}, %2;" : "=f"(r.x), "=f"(r.y) : "l"(v));
    return r;
}
__device__ __forceinline__ float warp_sum(float v) {
#pragma unroll
    for (int off = 16; off > 0; off >>= 1)
        v += __shfl_xor_sync(0xffffffffu, v, off);
    return v;
}

__device__ __forceinline__ void bar_up() {
    __syncthreads();
    if (threadIdx.x == 0) {
        __threadfence();
        atomicAdd(&g_bar, 1u);
        volatile unsigned* p = &g_bar;
        while (*p < NBLK) __nanosleep(64);
        __threadfence();
    }
    __syncthreads();
}
__device__ __forceinline__ void bar_down() {
    __syncthreads();
    if (threadIdx.x == 0) {
        __threadfence();
        atomicSub(&g_bar, 1u);
        volatile unsigned* p = &g_bar;
        while (*p != 0u) __nanosleep(64);
        __threadfence();
    }
    __syncthreads();
}

__device__ __forceinline__ void mbar_wait(unsigned mb, int par) {
    asm volatile(
        "{\n\t.reg .pred P1;\n\t"
        "W0_%=:\n\t"
        "mbarrier.try_wait.parity.acquire.cta.shared::cta.b64 P1, [%0], %1, 0x989680;\n\t"
        "@P1 bra.uni W1_%=;\n\t"
        "bra.uni W0_%=;\n\t"
        "W1_%=:\n\t}"
        :: "r"(mb), "r"(par) : "memory");
}

__device__ __forceinline__ void tma_bulk(unsigned sdst, const char* gsrc,
                                         unsigned bytes, unsigned mb) {
    asm volatile(
        "cp.async.bulk.shared::cluster.global.mbarrier::complete_tx::bytes "
        "[%0], [%1], %2, [%3];"
        :: "r"(sdst), "l"(gsrc), "r"(bytes), "r"(mb) : "memory");
}

// Fill one 64KB row slot: expect_tx(64KB) + 4 x 16KB bulks.
__device__ __forceinline__ void issue_row(unsigned sdst, const char* gsrc, unsigned mb) {
    asm volatile("mbarrier.arrive.expect_tx.shared.b64 _, [%0], %1;"
                 :: "r"(mb), "r"(ROW_BYTES) : "memory");
#pragma unroll
    for (int r = 0; r < 4; r++)
        tma_bulk(sdst + r * 16384, gsrc + (size_t)r * 16384, 16384, mb);
}

// ---------------------------------------------------------------------------
// Fused persistent kernel. grid = 148, block = 512, 1 CTA/SM.
// Phase B: block-level 64KB row slots with canonical full/empty mbarriers.
// ---------------------------------------------------------------------------
__global__ void __launch_bounds__(512, 1)
k_fused(const float* __restrict__ enc,
        const float* __restrict__ state,
        const float* __restrict__ attn_w,
        const float* __restrict__ attn_b,
        float* __restrict__ out)
{
    extern __shared__ char smem[];
    const int tid = threadIdx.x;
    const int b = tid >> 5;
    const int lane = tid & 31;
    const int c = blockIdx.x;
    const int s0 = c * CHUNK;
    const int s1 = min(s0 + CHUNK, S_LEN);
    const int n = max(s1 - s0, 0);

    const unsigned smem_u = (unsigned)__cvta_generic_to_shared(smem);
    const unsigned fbar0 = smem_u + FULL_OFF;
    const unsigned ebar0 = smem_u + EMPTY_OFF;
    const unsigned wbar = smem_u + WBAR_OFF;
    const char* grow = (const char*)enc;

    const int nrow = ((H2DIM - 1 - c) / NBLK) + 1;    // 6 or 7 weight rows

    // ---- init mbars; issue enc rows 0,1 ----
    if (tid == 0) {
#pragma unroll
        for (int k = 0; k < NSTAGE; k++) {
            asm volatile("mbarrier.init.shared.b64 [%0], 1;"
                         :: "r"(fbar0 + k * 8) : "memory");
            asm volatile("mbarrier.init.shared.b64 [%0], %1;"
                         :: "r"(ebar0 + k * 8), "r"(BATCH) : "memory");
        }
        asm volatile("mbarrier.init.shared.b64 [%0], 1;"
                     :: "r"(wbar) : "memory");
        asm volatile("fence.proxy.async.shared::cta;" ::: "memory");
#pragma unroll
        for (int k = 0; k < 2; k++)
            if (k < n)
                issue_row(smem_u + k * ROW_BYTES,
                          grow + (size_t)(s0 + k) * ROW_BYTES, fbar0 + k * 8);
        // weight rows into slot-2 area
        asm volatile("mbarrier.arrive.expect_tx.shared.b64 _, [%0], %1;"
                     :: "r"(wbar), "r"((unsigned)(nrow * SLICE_BYTES)) : "memory");
        for (int k = 0; k < nrow; k++) {
            int r = c + NBLK * k;
            tma_bulk(smem_u + WEIGHT_SMEM_OFF + k * SLICE_BYTES,
                     (const char*)attn_w + (size_t)r * SLICE_BYTES,
                     SLICE_BYTES, wbar);
        }
    }
    __syncthreads();                               // all mbar inits visible

    // ---- Phase A: GEMV, all CTAs. CTA c owns rows r = c + 148k ----
    float bias[7];
    for (int k = 0; k < nrow; k++)
        bias[k] = __ldg(attn_b + c + NBLK * k);

    unsigned long long st2[16];
    {
        const float4* sp = (const float4*)(state + b * H2DIM);
#pragma unroll
        for (int k = 0; k < 8; k++) {
            float4 v = __ldg(sp + lane + 32 * k);
            ulonglong2 t = *(ulonglong2*)&v;
            st2[2 * k] = t.x;
            st2[2 * k + 1] = t.y;
        }
    }

    mbar_wait(wbar, 0);

    for (int k = 0; k < nrow; k++) {
        const int r = c + NBLK * k;
        const ulonglong2* wp = (const ulonglong2*)(smem + WEIGHT_SMEM_OFF
                                                   + k * SLICE_BYTES);
        unsigned long long a2 = 0ull;
#pragma unroll
        for (int kk = 0; kk < 8; kk++) {
            ulonglong2 wv = wp[lane + 32 * kk];
            a2 = fma2(wv.x, st2[2 * kk], a2);
            a2 = fma2(wv.y, st2[2 * kk + 1], a2);
        }
        float2 f = upk2(a2);
        float tot = warp_sum(f.x + f.y);
        if (lane == 0)
            g_alt[b * H2DIM + r] = tot + bias[k];
    }

    // ---- barrier 1: g_alt ready everywhere ----
    bar_up();

    // ---- load alt; issue enc row 2 (slot-2 weights consumed) ----
    unsigned long long alt2[16];
    {
        const float4* ap = (const float4*)(g_alt + b * H2DIM);
#pragma unroll
        for (int k = 0; k < 8; k++) {
            float4 v = __ldg(ap + lane + 32 * k);
            ulonglong2 t = *(ulonglong2*)&v;
            alt2[2 * k] = t.x;
            alt2[2 * k + 1] = t.y;
        }
    }
    if (tid == 0 && 2 < n)
        issue_row(smem_u + 2 * ROW_BYTES,
                  grow + (size_t)(s0 + 2) * ROW_BYTES, fbar0 + 2 * 8);

    // ---- Phase B: online-softmax mainloop (full/empty mbarrier pipeline) ----
    unsigned long long acc2[16];
#pragma unroll
    for (int j = 0; j < 16; j++) acc2[j] = 0ull;
    float m = -1e30f, l = 0.f;

    int slot = 0, par = 0;
    for (int i = 0; i < n; i++) {
        // all threads wait on full[slot]
        mbar_wait(fbar0 + slot * 8, par);

        const ulonglong2* bp = (const ulonglong2*)(smem + slot * ROW_BYTES
                                                   + b * SLICE_BYTES);
        ulonglong2 e2[8];
#pragma unroll
        for (int k = 0; k < 8; k++) e2[k] = bp[lane + 32 * k];

        // logit
        unsigned long long w2 = 0ull;
#pragma unroll
        for (int k = 0; k < 8; k++) {
            w2 = fma2(e2[k].x, alt2[2 * k], w2);
            w2 = fma2(e2[k].y, alt2[2 * k + 1], w2);
        }
        float2 wp2 = upk2(w2);
        float w = warp_sum(wp2.x + wp2.y);

        // online softmax update (warp-uniform)
        if (w > m) {
            float sc = __expf(m - w);
            m = w;
            l *= sc;
            unsigned long long sc2 = pk2(sc, sc);
#pragma unroll
            for (int j = 0; j < 16; j++) acc2[j] = mul2(acc2[j], sc2);
        }
        float p = __expf(w - m);
        l += p;
        unsigned long long p2 = pk2(p, p);
#pragma unroll
        for (int k = 0; k < 8; k++) {
            acc2[2 * k]     = fma2(p2, e2[k].x, acc2[2 * k]);
            acc2[2 * k + 1] = fma2(p2, e2[k].y, acc2[2 * k + 1]);
        }
        if (lane == 0) g_wraw[b * S_LEN + s0 + i] = w;

        // slot drained by this warp: warp-ordered release arrive on empty[slot]
        __syncwarp();
        if (lane == 0)
            asm volatile("mbarrier.arrive.shared.b64 _, [%0];"
                         :: "r"(ebar0 + slot * 8) : "memory");

        // producer: refill after acquiring empty (16 arrivals = all drained)
        if (tid == 0) {
            int nxt = i + NSTAGE;
            if (nxt < n) {
                mbar_wait(ebar0 + slot * 8, par);
                issue_row(smem_u + slot * ROW_BYTES,
                          grow + (size_t)(s0 + nxt) * ROW_BYTES, fbar0 + slot * 8);
            }
        }

        if (++slot == NSTAGE) { slot = 0; par ^= 1; }
    }

    if (lane == 0) {
        g_m[c * BATCH + b] = m;
        g_l[c * BATCH + b] = l;
    }
    float4* outp = (float4*)(g_acc + ((size_t)c * BATCH + b) * H2DIM);
#pragma unroll
    for (int k = 0; k < 8; k++) {
        float2 a = upk2(acc2[2 * k]);
        float2 bq = upk2(acc2[2 * k + 1]);
        outp[lane + 32 * k] = make_float4(a.x, a.y, bq.x, bq.y);
    }

    // ---- barrier 2: all partials ready ----
    bar_down();

    // ---- Phase C: finish. 256 tiles over 148 blocks ----
    float* sfin = (float*)smem;
    float* s_coef = sfin;                           // [148]
    float* s_part = sfin + 160;                     // [512]
    float* s_ml   = sfin + 160 + 512;               // M, invL

#pragma unroll 1
    for (int pass = 0; pass < 2; pass++) {
        int T = (pass == 0) ? c : c + NBLK;
        if (T >= 256) break;
        const int isApplied = (T < 128);
        const int W = isApplied ? T : T - 128;
        const int bb = W >> 3;

        if (tid < 32) {
            float mx = -1e30f;
            for (int c2 = tid; c2 < NBLK; c2 += 32)
                mx = fmaxf(mx, g_m[c2 * BATCH + bb]);
#pragma unroll
            for (int off = 16; off > 0; off >>= 1)
                mx = fmaxf(mx, __shfl_xor_sync(0xffffffffu, mx, off));
            float ls = 0.f;
            for (int c2 = tid; c2 < NBLK; c2 += 32)
                ls += __expf(g_m[c2 * BATCH + bb] - mx) * g_l[c2 * BATCH + bb];
            ls = warp_sum(ls);
            if (tid == 0) { s_ml[0] = mx; s_ml[1] = 1.f / ls; }
        }
        __syncthreads();
        const float M = s_ml[0], invL = s_ml[1];

        if (isApplied) {
            if (tid < NBLK) s_coef[tid] = __expf(g_m[tid * BATCH + bb] - M);
            __syncthreads();
            const int g = tid >> 7;
            const int doff = tid & 127;
            const int d = (W & 7) * 128 + doff;
            float a = 0.f;
#pragma unroll
            for (int k = 0; k < 37; k++) {           // 148 = 4 * 37
                int c2 = g + 4 * k;
                a = fmaf(s_coef[c2],
                         g_acc[((size_t)c2 * BATCH + bb) * H2DIM + d], a);
            }
            s_part[tid] = a;
            __syncthreads();
            if (tid < 128) {
                float v = s_part[tid] + s_part[128 + tid]
                        + s_part[256 + tid] + s_part[384 + tid];
                out[bb * H2DIM + d] = v * invL;
            }
            __syncthreads();
        } else {
            const int s = (W & 7) * 512 + tid;
            out[BATCH * H2DIM + bb * S_LEN + s] =
                __expf(g_wraw[bb * S_LEN + s] - M) * invL;
            __syncthreads();
        }
    }
}

// ---------------------------------------------------------------------------
extern "C" void kernel_launch(void* const* d_in, const int* in_sizes, int n_in,
                              void* d_out, int out_size)
{
    const float* enc    = (const float*)d_in[0];
    const float* state  = (const float*)d_in[1];
    const float* attn_w = (const float*)d_in[3];
    const float* attn_b = (const float*)d_in[4];
    float* out = (float*)d_out;

    cudaFuncSetAttribute(k_fused,
        cudaFuncAttributeMaxDynamicSharedMemorySize, MAIN_SMEM);

    k_fused<<<NBLK, 512, MAIN_SMEM>>>(enc, state, attn_w, attn_b, out);
}

// round 14
// speedup vs baseline: 1.0010x; 1.0010x over previous
#include <cuda_runtime.h>
#include <math.h>

#define S_LEN 4096
#define BATCH 16
#define H2DIM 1024
#define NBLK 152                                  // GB300: 152 SMs
#define CHUNK 27                                  // ceil(4096/152)
#define ROW_BYTES (BATCH * H2DIM * 4)             // 64KB per s-row
#define SLICE_BYTES (H2DIM * 4)                   // 4KB per (s,b) slice
#define NSTAGE 3
#define MBAR_OFF (NSTAGE * ROW_BYTES)
#define WBAR_OFF (MBAR_OFF + 16 * NSTAGE * 8)     // weight-prefetch mbar
#define MAIN_SMEM (WBAR_OFF + 8)
#define WEIGHT_SMEM_OFF (2 * ROW_BYTES)           // weights staged over slot 2

// Scratch (allocation-free contract)
__device__ float g_alt[BATCH * H2DIM];            // altered_state (+bias)
__device__ float g_wraw[BATCH * S_LEN];
__device__ float g_m[NBLK * BATCH];
__device__ float g_l[NBLK * BATCH];
__device__ float g_acc[(size_t)NBLK * BATCH * H2DIM];
__device__ unsigned g_bar;                        // up/down grid barrier (self-cleaning)

// ---- packed f32x2 helpers ----------------------------------------------------
__device__ __forceinline__ unsigned long long fma2(unsigned long long a,
                                                   unsigned long long b,
                                                   unsigned long long c) {
    unsigned long long d;
    asm("fma.rn.f32x2 %0, %1, %2, %3;" : "=l"(d) : "l"(a), "l"(b), "l"(c));
    return d;
}
__device__ __forceinline__ unsigned long long mul2(unsigned long long a,
                                                   unsigned long long b) {
    unsigned long long d;
    asm("mul.rn.f32x2 %0, %1, %2;" : "=l"(d) : "l"(a), "l"(b));
    return d;
}
__device__ __forceinline__ unsigned long long pk2(float lo, float hi) {
    unsigned long long r;
    asm("mov.b64 %0, {%1, %2};" : "=l"(r) : "f"(lo), "f"(hi));
    return r;
}
__device__ __forceinline__ float2 upk2(unsigned long long v) {
    float2 r;
    asm("mov.b64 {%0, %1}, %2;" : "=f"(r.x), "=f"(r.y) : "l"(v));
    return r;
}
__device__ __forceinline__ float warp_sum(float v) {
#pragma unroll
    for (int off = 16; off > 0; off >>= 1)
        v += __shfl_xor_sync(0xffffffffu, v, off);
    return v;
}

__device__ __forceinline__ void bar_up() {
    __syncthreads();
    if (threadIdx.x == 0) {
        __threadfence();
        atomicAdd(&g_bar, 1u);
        volatile unsigned* p = &g_bar;
        while (*p < NBLK) __nanosleep(64);
        __threadfence();
    }
    __syncthreads();
}
__device__ __forceinline__ void bar_down() {
    __syncthreads();
    if (threadIdx.x == 0) {
        __threadfence();
        atomicSub(&g_bar, 1u);
        volatile unsigned* p = &g_bar;
        while (*p != 0u) __nanosleep(64);
        __threadfence();
    }
    __syncthreads();
}

__device__ __forceinline__ void mbar_wait(unsigned mb, int par) {
    asm volatile(
        "{\n\t.reg .pred P1;\n\t"
        "W0_%=:\n\t"
        "mbarrier.try_wait.parity.acquire.cta.shared::cta.b64 P1, [%0], %1, 0x989680;\n\t"
        "@P1 bra.uni W1_%=;\n\t"
        "bra.uni W0_%=;\n\t"
        "W1_%=:\n\t}"
        :: "r"(mb), "r"(par) : "memory");
}

__device__ __forceinline__ void tma_bulk(unsigned sdst, const char* gsrc,
                                         unsigned bytes, unsigned mb) {
    asm volatile(
        "cp.async.bulk.shared::cluster.global.mbarrier::complete_tx::bytes "
        "[%0], [%1], %2, [%3];"
        :: "r"(sdst), "l"(gsrc), "r"(bytes), "r"(mb) : "memory");
}
__device__ __forceinline__ void tma_slice(unsigned sdst, const char* gsrc, unsigned mb) {
    asm volatile("mbarrier.arrive.expect_tx.shared.b64 _, [%0], %1;"
                 :: "r"(mb), "r"(SLICE_BYTES) : "memory");
    tma_bulk(sdst, gsrc, SLICE_BYTES, mb);
}

// ---------------------------------------------------------------------------
// Fused persistent kernel. grid = 152, block = 512, 1 CTA/SM.
// Phase B: per-warp TMA rings (proven R7/R12 structure).
// ---------------------------------------------------------------------------
__global__ void __launch_bounds__(512, 1)
k_fused(const float* __restrict__ enc,
        const float* __restrict__ state,
        const float* __restrict__ attn_w,
        const float* __restrict__ attn_b,
        float* __restrict__ out)
{
    extern __shared__ char smem[];
    const int tid = threadIdx.x;
    const int b = tid >> 5;
    const int lane = tid & 31;
    const int c = blockIdx.x;
    const int s0 = c * CHUNK;
    const int s1 = min(s0 + CHUNK, S_LEN);
    const int n = max(s1 - s0, 0);

    const unsigned smem_u = (unsigned)__cvta_generic_to_shared(smem);
    const unsigned slice0 = smem_u + b * SLICE_BYTES;
    const unsigned mbar0 = smem_u + MBAR_OFF + b * (NSTAGE * 8);
    const unsigned wbar = smem_u + WBAR_OFF;
    const char* gbase = (const char*)enc + (size_t)b * SLICE_BYTES;

    const int nrow = ((H2DIM - 1 - c) / NBLK) + 1;    // 7 (c<112) or 6

    // ---- per-warp mbar init + enc slots 0,1 issue; tid0 also inits wbar ----
    if (lane == 0) {
#pragma unroll
        for (int k = 0; k < NSTAGE; k++)
            asm volatile("mbarrier.init.shared.b64 [%0], 1;"
                         :: "r"(mbar0 + k * 8) : "memory");
        if (tid == 0)
            asm volatile("mbarrier.init.shared.b64 [%0], 1;"
                         :: "r"(wbar) : "memory");
        asm volatile("fence.proxy.async.shared::cta;" ::: "memory");
#pragma unroll
        for (int k = 0; k < 2; k++)
            if (k < n)
                tma_slice(slice0 + k * ROW_BYTES,
                          gbase + (size_t)(s0 + k) * ROW_BYTES, mbar0 + k * 8);
    }
    __syncthreads();                               // wbar init visible to all

    // ---- Phase A: GEMV, all CTAs. CTA c owns rows r = c + 152k ----
    if (tid == 0) {
        asm volatile("mbarrier.arrive.expect_tx.shared.b64 _, [%0], %1;"
                     :: "r"(wbar), "r"((unsigned)(nrow * SLICE_BYTES)) : "memory");
        for (int k = 0; k < nrow; k++) {
            int r = c + NBLK * k;
            tma_bulk(smem_u + WEIGHT_SMEM_OFF + k * SLICE_BYTES,
                     (const char*)attn_w + (size_t)r * SLICE_BYTES,
                     SLICE_BYTES, wbar);
        }
    }

    float bias[7];
    for (int k = 0; k < nrow; k++)
        bias[k] = __ldg(attn_b + c + NBLK * k);

    unsigned long long st2[16];
    {
        const float4* sp = (const float4*)(state + b * H2DIM);
#pragma unroll
        for (int k = 0; k < 8; k++) {
            float4 v = __ldg(sp + lane + 32 * k);
            ulonglong2 t = *(ulonglong2*)&v;
            st2[2 * k] = t.x;
            st2[2 * k + 1] = t.y;
        }
    }

    mbar_wait(wbar, 0);

    for (int k = 0; k < nrow; k++) {
        const int r = c + NBLK * k;
        const ulonglong2* wp = (const ulonglong2*)(smem + WEIGHT_SMEM_OFF
                                                   + k * SLICE_BYTES);
        unsigned long long a2 = 0ull;
#pragma unroll
        for (int kk = 0; kk < 8; kk++) {
            ulonglong2 wv = wp[lane + 32 * kk];
            a2 = fma2(wv.x, st2[2 * kk], a2);
            a2 = fma2(wv.y, st2[2 * kk + 1], a2);
        }
        float2 f = upk2(a2);
        float tot = warp_sum(f.x + f.y);
        if (lane == 0)
            g_alt[b * H2DIM + r] = tot + bias[k];
    }

    // ---- barrier 1: g_alt ready everywhere ----
    bar_up();

    // ---- load alt, issue slot 2 (slot-2 smem area now free) ----
    unsigned long long alt2[16];
    {
        const float4* ap = (const float4*)(g_alt + b * H2DIM);
#pragma unroll
        for (int k = 0; k < 8; k++) {
            float4 v = __ldg(ap + lane + 32 * k);
            ulonglong2 t = *(ulonglong2*)&v;
            alt2[2 * k] = t.x;
            alt2[2 * k + 1] = t.y;
        }
    }
    if (lane == 0 && 2 < n)
        tma_slice(slice0 + 2 * ROW_BYTES,
                  gbase + (size_t)(s0 + 2) * ROW_BYTES, mbar0 + 2 * 8);

    // ---- Phase B: online-softmax mainloop (per-warp TMA rings) ----
    unsigned long long acc2[16];
#pragma unroll
    for (int j = 0; j < 16; j++) acc2[j] = 0ull;
    float m = -1e30f, l = 0.f;

    int slot = 0, par = 0;
    for (int i = 0; i < n; i++) {
        const unsigned mb = mbar0 + slot * 8;
        mbar_wait(mb, par);

        const ulonglong2* bp = (const ulonglong2*)(smem + slot * ROW_BYTES
                                                   + b * SLICE_BYTES);
        ulonglong2 e2[8];
#pragma unroll
        for (int k = 0; k < 8; k++) e2[k] = bp[lane + 32 * k];

        int nxt = i + NSTAGE;
        if (nxt < n && lane == 0)
            tma_slice(slice0 + slot * ROW_BYTES,
                      gbase + (size_t)(s0 + nxt) * ROW_BYTES, mb);

        unsigned long long w2 = 0ull;
#pragma unroll
        for (int k = 0; k < 8; k++) {
            w2 = fma2(e2[k].x, alt2[2 * k], w2);
            w2 = fma2(e2[k].y, alt2[2 * k + 1], w2);
        }
        float2 wp2 = upk2(w2);
        float w = warp_sum(wp2.x + wp2.y);

        if (w > m) {                               // warp-uniform
            float sc = __expf(m - w);
            m = w;
            l *= sc;
            unsigned long long sc2 = pk2(sc, sc);
#pragma unroll
            for (int j = 0; j < 16; j++) acc2[j] = mul2(acc2[j], sc2);
        }
        float p = __expf(w - m);
        l += p;
        unsigned long long p2 = pk2(p, p);
#pragma unroll
        for (int k = 0; k < 8; k++) {
            acc2[2 * k]     = fma2(p2, e2[k].x, acc2[2 * k]);
            acc2[2 * k + 1] = fma2(p2, e2[k].y, acc2[2 * k + 1]);
        }
        if (lane == 0) g_wraw[b * S_LEN + s0 + i] = w;

        if (++slot == NSTAGE) { slot = 0; par ^= 1; }
    }

    if (lane == 0) {
        g_m[c * BATCH + b] = m;
        g_l[c * BATCH + b] = l;
    }
    float4* outp = (float4*)(g_acc + ((size_t)c * BATCH + b) * H2DIM);
#pragma unroll
    for (int k = 0; k < 8; k++) {
        float2 a = upk2(acc2[2 * k]);
        float2 bq = upk2(acc2[2 * k + 1]);
        outp[lane + 32 * k] = make_float4(a.x, a.y, bq.x, bq.y);
    }

    // ---- barrier 2: all partials ready ----
    bar_down();

    // ---- Phase C: finish. 256 tiles over 152 blocks ----
    float* sfin = (float*)smem;
    float* s_coef = sfin;                           // [152]
    float* s_part = sfin + 160;                     // [512]
    float* s_ml   = sfin + 160 + 512;               // M, invL

#pragma unroll 1
    for (int pass = 0; pass < 2; pass++) {
        int T = (pass == 0) ? c : c + NBLK;
        if (T >= 256) break;
        const int isApplied = (T < 128);
        const int W = isApplied ? T : T - 128;
        const int bb = W >> 3;

        if (tid < 32) {
            float mx = -1e30f;
            for (int c2 = tid; c2 < NBLK; c2 += 32)
                mx = fmaxf(mx, g_m[c2 * BATCH + bb]);
#pragma unroll
            for (int off = 16; off > 0; off >>= 1)
                mx = fmaxf(mx, __shfl_xor_sync(0xffffffffu, mx, off));
            float ls = 0.f;
            for (int c2 = tid; c2 < NBLK; c2 += 32)
                ls += __expf(g_m[c2 * BATCH + bb] - mx) * g_l[c2 * BATCH + bb];
            ls = warp_sum(ls);
            if (tid == 0) { s_ml[0] = mx; s_ml[1] = 1.f / ls; }
        }
        __syncthreads();
        const float M = s_ml[0], invL = s_ml[1];

        if (isApplied) {
            if (tid < NBLK) s_coef[tid] = __expf(g_m[tid * BATCH + bb] - M);
            __syncthreads();
            const int g = tid >> 7;                  // 0..3
            const int doff = tid & 127;
            const int d = (W & 7) * 128 + doff;
            float a = 0.f;
#pragma unroll
            for (int k = 0; k < 38; k++) {           // 152 = 4 * 38
                int c2 = g + 4 * k;
                a = fmaf(s_coef[c2],
                         g_acc[((size_t)c2 * BATCH + bb) * H2DIM + d], a);
            }
            s_part[tid] = a;
            __syncthreads();
            if (tid < 128) {
                float v = s_part[tid] + s_part[128 + tid]
                        + s_part[256 + tid] + s_part[384 + tid];
                out[bb * H2DIM + d] = v * invL;
            }
            __syncthreads();
        } else {
            const int s = (W & 7) * 512 + tid;
            out[BATCH * H2DIM + bb * S_LEN + s] =
                __expf(g_wraw[bb * S_LEN + s] - M) * invL;
            __syncthreads();
        }
    }
}

// ---------------------------------------------------------------------------
extern "C" void kernel_launch(void* const* d_in, const int* in_sizes, int n_in,
                              void* d_out, int out_size)
{
    const float* enc    = (const float*)d_in[0];
    const float* state  = (const float*)d_in[1];
    const float* attn_w = (const float*)d_in[3];
    const float* attn_b = (const float*)d_in[4];
    float* out = (float*)d_out;

    cudaFuncSetAttribute(k_fused,
        cudaFuncAttributeMaxDynamicSharedMemorySize, MAIN_SMEM);

    k_fused<<<NBLK, 512, MAIN_SMEM>>>(enc, state, attn_w, attn_b, out);
}

// round 15
// speedup vs baseline: 1.0109x; 1.0099x over previous
#include <cuda_runtime.h>
#include <math.h>

#define S_LEN 4096
#define BATCH 16
#define H2DIM 1024
#define NBLK 152
#define CHUNK 27                                  // ceil(4096/152)
#define ROW_BYTES (BATCH * H2DIM * 4)             // 64KB per s-row
#define SLICE_BYTES (H2DIM * 4)                   // 4KB per (s,b) slice
#define NSTAGE 3
#define MBAR_OFF (NSTAGE * ROW_BYTES)
#define MAIN_SMEM (MBAR_OFF + 16 * NSTAGE * 8)

// Scratch (allocation-free contract)
__device__ float g_alt[BATCH * H2DIM];            // altered_state (+bias)
__device__ float g_wraw[BATCH * S_LEN];
__device__ float g_m[NBLK * BATCH];
__device__ float g_l[NBLK * BATCH];
__device__ float g_acc[(size_t)NBLK * BATCH * H2DIM];

// ---- packed f32x2 helpers ----------------------------------------------------
__device__ __forceinline__ unsigned long long fma2(unsigned long long a,
                                                   unsigned long long b,
                                                   unsigned long long c) {
    unsigned long long d;
    asm("fma.rn.f32x2 %0, %1, %2, %3;" : "=l"(d) : "l"(a), "l"(b), "l"(c));
    return d;
}
__device__ __forceinline__ unsigned long long mul2(unsigned long long a,
                                                   unsigned long long b) {
    unsigned long long d;
    asm("mul.rn.f32x2 %0, %1, %2;" : "=l"(d) : "l"(a), "l"(b));
    return d;
}
__device__ __forceinline__ unsigned long long pk2(float lo, float hi) {
    unsigned long long r;
    asm("mov.b64 %0, {%1, %2};" : "=l"(r) : "f"(lo), "f"(hi));
    return r;
}
__device__ __forceinline__ float2 upk2(unsigned long long v) {
    float2 r;
    asm("mov.b64 {%0, %1}, %2;" : "=f"(r.x), "=f"(r.y) : "l"(v));
    return r;
}
__device__ __forceinline__ float warp_sum(float v) {
#pragma unroll
    for (int off = 16; off > 0; off >>= 1)
        v += __shfl_xor_sync(0xffffffffu, v, off);
    return v;
}

__device__ __forceinline__ void mbar_wait(unsigned mb, int par) {
    asm volatile(
        "{\n\t.reg .pred P1;\n\t"
        "W0_%=:\n\t"
        "mbarrier.try_wait.parity.acquire.cta.shared::cta.b64 P1, [%0], %1, 0x989680;\n\t"
        "@P1 bra.uni W1_%=;\n\t"
        "bra.uni W0_%=;\n\t"
        "W1_%=:\n\t}"
        :: "r"(mb), "r"(par) : "memory");
}

__device__ __forceinline__ void tma_bulk(unsigned sdst, const char* gsrc,
                                         unsigned bytes, unsigned mb) {
    asm volatile(
        "cp.async.bulk.shared::cluster.global.mbarrier::complete_tx::bytes "
        "[%0], [%1], %2, [%3];"
        :: "r"(sdst), "l"(gsrc), "r"(bytes), "r"(mb) : "memory");
}
__device__ __forceinline__ void tma_slice(unsigned sdst, const char* gsrc, unsigned mb) {
    asm volatile("mbarrier.arrive.expect_tx.shared.b64 _, [%0], %1;"
                 :: "r"(mb), "r"(SLICE_BYTES) : "memory");
    tma_bulk(sdst, gsrc, SLICE_BYTES, mb);
}

// ---------------------------------------------------------------------------
// Kernel 1: altered_state = state @ attn_w^T + attn_b.
// grid=152, block=512. CTA c owns rows r = c + 152k (7 rows for c<112, else 6),
// TMA-staged into smem. Warp b owns batch b; state[b] in registers.
// ---------------------------------------------------------------------------
__global__ void __launch_bounds__(512, 1)
k_altered(const float* __restrict__ state,
          const float* __restrict__ attn_w,
          const float* __restrict__ attn_b)
{
    __shared__ __align__(128) char wsm[7 * SLICE_BYTES];
    __shared__ __align__(8) unsigned long long wbar_s;
    const int tid = threadIdx.x;
    const int b = tid >> 5;
    const int lane = tid & 31;
    const int c = blockIdx.x;
    const int nrow = ((H2DIM - 1 - c) / NBLK) + 1;

    const unsigned wsm_u = (unsigned)__cvta_generic_to_shared(wsm);
    const unsigned wbar = (unsigned)__cvta_generic_to_shared(&wbar_s);

    if (tid == 0) {
        asm volatile("mbarrier.init.shared.b64 [%0], 1;" :: "r"(wbar) : "memory");
        asm volatile("fence.proxy.async.shared::cta;" ::: "memory");
        asm volatile("mbarrier.arrive.expect_tx.shared.b64 _, [%0], %1;"
                     :: "r"(wbar), "r"((unsigned)(nrow * SLICE_BYTES)) : "memory");
        for (int k = 0; k < nrow; k++) {
            int r = c + NBLK * k;
            tma_bulk(wsm_u + k * SLICE_BYTES,
                     (const char*)attn_w + (size_t)r * SLICE_BYTES,
                     SLICE_BYTES, wbar);
        }
    }
    __syncthreads();                               // wbar init visible

    float bias[7];
    for (int k = 0; k < nrow; k++)
        bias[k] = __ldg(attn_b + c + NBLK * k);

    unsigned long long st2[16];
    {
        const float4* sp = (const float4*)(state + b * H2DIM);
#pragma unroll
        for (int k = 0; k < 8; k++) {
            float4 v = __ldg(sp + lane + 32 * k);
            ulonglong2 t = *(ulonglong2*)&v;
            st2[2 * k] = t.x;
            st2[2 * k + 1] = t.y;
        }
    }

    mbar_wait(wbar, 0);

    for (int k = 0; k < nrow; k++) {
        const int r = c + NBLK * k;
        const ulonglong2* wp = (const ulonglong2*)(wsm + k * SLICE_BYTES);
        unsigned long long a2 = 0ull;
#pragma unroll
        for (int kk = 0; kk < 8; kk++) {
            ulonglong2 wv = wp[lane + 32 * kk];
            a2 = fma2(wv.x, st2[2 * kk], a2);
            a2 = fma2(wv.y, st2[2 * kk + 1], a2);
        }
        float2 f = upk2(a2);
        float tot = warp_sum(f.x + f.y);
        if (lane == 0)
            g_alt[b * H2DIM + r] = tot + bias[k];
    }
}

// ---------------------------------------------------------------------------
// Kernel 2: single-pass online softmax, per-warp TMA rings (R4 structure).
// grid=152, block=512, warp b owns batch b.
// ---------------------------------------------------------------------------
__global__ void __launch_bounds__(512, 1)
k_mainpass(const float* __restrict__ enc)
{
    extern __shared__ char smem[];
    const int tid = threadIdx.x;
    const int b = tid >> 5;
    const int lane = tid & 31;
    const int c = blockIdx.x;
    const int s0 = c * CHUNK;
    const int s1 = min(s0 + CHUNK, S_LEN);
    const int n = max(s1 - s0, 0);

    const unsigned smem_u = (unsigned)__cvta_generic_to_shared(smem);
    const unsigned slice0 = smem_u + b * SLICE_BYTES;
    const unsigned mbar0 = smem_u + MBAR_OFF + b * (NSTAGE * 8);
    const char* gbase = (const char*)enc + (size_t)b * SLICE_BYTES;

    if (lane == 0) {
#pragma unroll
        for (int k = 0; k < NSTAGE; k++)
            asm volatile("mbarrier.init.shared.b64 [%0], 1;"
                         :: "r"(mbar0 + k * 8) : "memory");
        asm volatile("fence.proxy.async.shared::cta;" ::: "memory");
#pragma unroll
        for (int k = 0; k < NSTAGE; k++)
            if (k < n)
                tma_slice(slice0 + k * ROW_BYTES,
                          gbase + (size_t)(s0 + k) * ROW_BYTES, mbar0 + k * 8);
    }

    // alt slice (overlaps TMA prologue)
    unsigned long long alt2[16];
    {
        const float4* ap = (const float4*)(g_alt + b * H2DIM);
#pragma unroll
        for (int k = 0; k < 8; k++) {
            float4 v = __ldg(ap + lane + 32 * k);
            ulonglong2 t = *(ulonglong2*)&v;
            alt2[2 * k] = t.x;
            alt2[2 * k + 1] = t.y;
        }
    }

    unsigned long long acc2[16];
#pragma unroll
    for (int j = 0; j < 16; j++) acc2[j] = 0ull;
    float m = -1e30f, l = 0.f;

    int slot = 0, par = 0;
    for (int i = 0; i < n; i++) {
        const unsigned mb = mbar0 + slot * 8;
        mbar_wait(mb, par);

        const ulonglong2* bp = (const ulonglong2*)(smem + slot * ROW_BYTES
                                                   + b * SLICE_BYTES);
        ulonglong2 e2[8];
#pragma unroll
        for (int k = 0; k < 8; k++) e2[k] = bp[lane + 32 * k];

        int nxt = i + NSTAGE;
        if (nxt < n && lane == 0)
            tma_slice(slice0 + slot * ROW_BYTES,
                      gbase + (size_t)(s0 + nxt) * ROW_BYTES, mb);

        unsigned long long w2 = 0ull;
#pragma unroll
        for (int k = 0; k < 8; k++) {
            w2 = fma2(e2[k].x, alt2[2 * k], w2);
            w2 = fma2(e2[k].y, alt2[2 * k + 1], w2);
        }
        float2 wp2 = upk2(w2);
        float w = warp_sum(wp2.x + wp2.y);

        if (w > m) {                               // warp-uniform
            float sc = __expf(m - w);
            m = w;
            l *= sc;
            unsigned long long sc2 = pk2(sc, sc);
#pragma unroll
            for (int j = 0; j < 16; j++) acc2[j] = mul2(acc2[j], sc2);
        }
        float p = __expf(w - m);
        l += p;
        unsigned long long p2 = pk2(p, p);
#pragma unroll
        for (int k = 0; k < 8; k++) {
            acc2[2 * k]     = fma2(p2, e2[k].x, acc2[2 * k]);
            acc2[2 * k + 1] = fma2(p2, e2[k].y, acc2[2 * k + 1]);
        }
        if (lane == 0) g_wraw[b * S_LEN + s0 + i] = w;

        if (++slot == NSTAGE) { slot = 0; par ^= 1; }
    }

    if (lane == 0) {
        g_m[c * BATCH + b] = m;
        g_l[c * BATCH + b] = l;
    }
    float4* outp = (float4*)(g_acc + ((size_t)c * BATCH + b) * H2DIM);
#pragma unroll
    for (int k = 0; k < 8; k++) {
        float2 a = upk2(acc2[2 * k]);
        float2 bq = upk2(acc2[2 * k + 1]);
        outp[lane + 32 * k] = make_float4(a.x, a.y, bq.x, bq.y);
    }
}

// ---------------------------------------------------------------------------
// Kernel 3: finish. grid = (BATCH, 24), block 512.
// t in [0,16): attention_applied d-tile of 64, 8 parallel c2-groups (19 each).
// t in [16,24): normalized_weights s-tile of 512.
// ---------------------------------------------------------------------------
__global__ void __launch_bounds__(512, 2)
k_finish(float* __restrict__ out)
{
    const int b = blockIdx.x;
    const int t = blockIdx.y;
    const int tid = threadIdx.x;
    __shared__ float sM, sInvL;
    __shared__ float s_coef[NBLK];
    __shared__ float s_part[512];

    if (tid < 32) {
        float mx = -1e30f;
        for (int c2 = tid; c2 < NBLK; c2 += 32)
            mx = fmaxf(mx, g_m[c2 * BATCH + b]);
#pragma unroll
        for (int off = 16; off > 0; off >>= 1)
            mx = fmaxf(mx, __shfl_xor_sync(0xffffffffu, mx, off));
        float ls = 0.f;
        for (int c2 = tid; c2 < NBLK; c2 += 32)
            ls += __expf(g_m[c2 * BATCH + b] - mx) * g_l[c2 * BATCH + b];
        ls = warp_sum(ls);
        if (tid == 0) { sM = mx; sInvL = 1.f / ls; }
    }
    __syncthreads();
    const float M = sM, invL = sInvL;

    if (t < 16) {
        if (tid < NBLK) s_coef[tid] = __expf(g_m[tid * BATCH + b] - M);
        __syncthreads();
        const int doff = tid & 63;
        const int g = tid >> 6;                 // 0..7
        const int d = t * 64 + doff;
        float a = 0.f;
#pragma unroll
        for (int k = 0; k < 19; k++) {          // 152 = 8 * 19
            int c2 = g + 8 * k;
            a = fmaf(s_coef[c2], g_acc[((size_t)c2 * BATCH + b) * H2DIM + d], a);
        }
        s_part[tid] = a;
        __syncthreads();
        if (tid < 64) {
            float v = 0.f;
#pragma unroll
            for (int gg = 0; gg < 8; gg++) v += s_part[gg * 64 + tid];
            out[b * H2DIM + d] = v * invL;
        }
    } else {
        const int s = (t - 16) * 512 + tid;
        out[BATCH * H2DIM + b * S_LEN + s] =
            __expf(g_wraw[b * S_LEN + s] - M) * invL;
    }
}

// ---------------------------------------------------------------------------
extern "C" void kernel_launch(void* const* d_in, const int* in_sizes, int n_in,
                              void* d_out, int out_size)
{
    const float* enc    = (const float*)d_in[0];
    const float* state  = (const float*)d_in[1];
    const float* attn_w = (const float*)d_in[3];
    const float* attn_b = (const float*)d_in[4];
    float* out = (float*)d_out;

    cudaFuncSetAttribute(k_mainpass,
        cudaFuncAttributeMaxDynamicSharedMemorySize, MAIN_SMEM);

    k_altered<<<NBLK, 512>>>(state, attn_w, attn_b);
    k_mainpass<<<NBLK, 512, MAIN_SMEM>>>(enc);
    k_finish<<<dim3(BATCH, 24), 512>>>(out);
}